// round 14
// baseline (speedup 1.0000x reference)
#include <cuda_runtime.h>
#include <math.h>

#define EPSF 1e-4f
typedef unsigned long long u64;

__device__ __forceinline__ u64 pack2(float x){
  u64 r; unsigned xi = __float_as_uint(x);
  asm("mov.b64 %0, {%1, %1};" : "=l"(r) : "r"(xi));
  return r;
}
__device__ __forceinline__ void fma2(u64 &acc, u64 a, u64 b){
  asm("fma.rn.f32x2 %0, %1, %2, %0;" : "+l"(acc) : "l"(a), "l"(b));
}
__device__ __forceinline__ float2 unpack2(u64 v){
  unsigned lo, hi;
  asm("mov.b64 {%0, %1}, %2;" : "=r"(lo), "=r"(hi) : "l"(v));
  return make_float2(__uint_as_float(lo), __uint_as_float(hi));
}
__device__ __forceinline__ float rsum32(float v){
  #pragma unroll
  for (int o=16;o;o>>=1) v += __shfl_xor_sync(0xffffffffu, v, o);
  return v;
}
__device__ __forceinline__ float rsum16(float v){
  #pragma unroll
  for (int o=8;o;o>>=1) v += __shfl_xor_sync(0xffffffffu, v, o);
  return v;
}
__device__ __forceinline__ float rmax16(float v){
  #pragma unroll
  for (int o=8;o;o>>=1) v = fmaxf(v, __shfl_xor_sync(0xffffffffu, v, o));
  return v;
}
__device__ __forceinline__ float sigm(float x){ return 1.f/(1.f+expf(-x)); }
__device__ __forceinline__ float splus(float x){ return fmaxf(x,0.f)+log1pf(expf(-fabsf(x))); }

struct Smem {
  float sciT[260][2];
  float sh1T[128][2];
  float sct2[128][2];
  float sc[2][16][132];
  float smix[2][16][16];
  float satt[2][128];
  float sbuf[16][2][128];
  float ssp[2][16], smaM[2][16], sal[2][16], sgs[2][16];
  float ssq[2][16], sms[2][16], smm[2][16];
  float sraw[2][4][16];
  float sred[2][4][3];
  float snv[2], srl[2], sval[2];
  int   sidx[2];
};

__global__ void __launch_bounds__(512,1) cfrm_kernel(
   const int* __restrict__ tokens, const float* __restrict__ emb,
   const float* __restrict__ ln_g, const float* __restrict__ ln_b,
   const float* __restrict__ w1, const float* __restrict__ b1,
   const float* __restrict__ w2, const float* __restrict__ b2,
   const float* __restrict__ gate_w, const float* __restrict__ gate_b,
   const float* __restrict__ assign_w, const float* __restrict__ assign_b,
   const float* __restrict__ nov_w, const float* __restrict__ nov_b,
   const float* __restrict__ relax_w, const float* __restrict__ relax_b,
   const float* __restrict__ cc_w, const float* __restrict__ cc_b,
   const float* __restrict__ cs_w, const float* __restrict__ cs_b,
   const float* __restrict__ md_w, const float* __restrict__ md_b,
   const float* __restrict__ att_w, const float* __restrict__ att_b,
   const float* __restrict__ cw1, const float* __restrict__ cb1,
   const float* __restrict__ cw2, const float* __restrict__ cb2,
   float* __restrict__ out)
{
  extern __shared__ __align__(128) char smem_raw[];
  Smem* S = (Smem*)smem_raw;

  const int tid  = threadIdx.x;
  const int g    = tid >> 7;        // 0..3; batches are g<2
  const int ht   = tid & 127;
  const int lane = tid & 31;
  const int wg   = (tid >> 5) & 3;
  const int b    = blockIdx.x * 2 + (g & 1);

  const int j4  = tid & 31;
  const int isl = tid >> 5;

  for (int i = tid; i < 2*16*132; i += 512) ((float*)S->sc)[i] = 0.f;
  if (tid < 32){ ((float*)S->ssp)[tid] = 1.f; ((float*)S->smaM)[tid] = 0.f; }
  __syncthreads();

  for (int t = 0; t < 512; t++){
    if (g < 2){
      const int tok = tokens[b*512 + t];
      const float valid = (tok != 0) ? 1.f : 0.f;
      if (ht == 0) S->sval[g] = valid;
      const float e = emb[tok*128 + ht];
      float ps = rsum32(e);
      float pq = rsum32(e*e);
      if (lane == 0){ S->sred[g][wg][0] = ps; S->sred[g][wg][1] = pq; }
      S->sciT[ht][g] = e;
    }
    if (g == 2 && ht < 32){
      const int gb = lane >> 4;
      const int c  = lane & 15;
      float sp = S->ssp[gb][c];
      float m  = S->smaM[gb][c];
      float score = m + logf(1.f/(sp+EPSF)+EPSF);
      float mx = rmax16(score);
      float ex = expf(score - mx);
      float sm = rsum16(ex);
      float a  = ex / sm;
      S->sal[gb][c] = a;
      float u   = rsum16(a*sp);
      float ent = rsum16(-a*logf(fmaxf(a,1e-8f)));
      float mm2 = rmax16(m);
      float en  = mm2 + logf(rsum16(expf(m - mm2)));
      if (c == 0){ S->sciT[256][gb] = u; S->sciT[258][gb] = en; S->sciT[259][gb] = ent; }
    }
    __syncthreads(); // S1
    if (g < 2){
      const float e = S->sciT[ht][g];
      float mu = (S->sred[g][0][0]+S->sred[g][1][0]+S->sred[g][2][0]+S->sred[g][3][0]) * (1.f/128.f);
      float mq = (S->sred[g][0][1]+S->sred[g][1][1]+S->sred[g][2][1]+S->sred[g][3][1]) * (1.f/128.f);
      float var = mq - mu*mu;
      float te = (e - mu) * rsqrtf(var + 1e-5f) * ln_g[ht] + ln_b[ht];
      S->sciT[ht][g] = te;
      float core = 0.f;
      #pragma unroll
      for (int c = 0; c < 16; c++) core += S->sal[g][c] * S->sc[g][c][ht];
      S->sciT[128+ht][g] = core;
      float dv = 0.f;
      #pragma unroll
      for (int c = 0; c < 16; c++){ float dd = S->sc[g][c][ht] - core; dv += S->sal[g][c]*dd*dd; }
      dv = rsum32(dv);
      if (lane == 0) S->sred[g][wg][2] = dv;
    }
    __syncthreads(); // S2a
    if (tid < 2)
      S->sciT[257][tid] = (S->sred[tid][0][2]+S->sred[tid][1][2]+S->sred[tid][2][2]+S->sred[tid][3][2]) * (1.f/128.f);
    __syncthreads(); // S2b

    // ---- w1 [260,128] ----
    {
      u64 ax[2] = {0,0}, ay[2] = {0,0};
      const int lo = isl * 16;
      #pragma unroll
      for (int r = 0; r < 16; r++){
        const int i = lo + r;
        ulonglong2 w = *(const ulonglong2*)&w1[i*128 + j4*4];
        float2 x = *(const float2*)&S->sciT[i][0];
        u64 p0 = pack2(x.x), p1 = pack2(x.y);
        fma2(ax[0], p0, w.x); fma2(ay[0], p0, w.y);
        fma2(ax[1], p1, w.x); fma2(ay[1], p1, w.y);
      }
      if (isl < 4){
        const int i = 256 + isl;
        ulonglong2 w = *(const ulonglong2*)&w1[i*128 + j4*4];
        float2 x = *(const float2*)&S->sciT[i][0];
        u64 p0 = pack2(x.x), p1 = pack2(x.y);
        fma2(ax[0], p0, w.x); fma2(ay[0], p0, w.y);
        fma2(ax[1], p1, w.x); fma2(ay[1], p1, w.y);
      }
      #pragma unroll
      for (int b2 = 0; b2 < 2; b2++){
        float2 l = unpack2(ax[b2]), h2 = unpack2(ay[b2]);
        *(float4*)&S->sbuf[isl][b2][j4*4] = make_float4(l.x, l.y, h2.x, h2.y);
      }
    }
    __syncthreads(); // S3
    if (g < 2){
      float s = b1[ht];
      #pragma unroll
      for (int k = 0; k < 16; k++) s += S->sbuf[k][g][ht];
      S->sh1T[ht][g] = tanhf(s);
    }
    __syncthreads(); // S4

    // ---- w2 [128,128] ----
    {
      u64 ax[2] = {0,0}, ay[2] = {0,0};
      const int lo = isl * 8;
      #pragma unroll
      for (int r = 0; r < 8; r++){
        const int i = lo + r;
        ulonglong2 w = *(const ulonglong2*)&w2[i*128 + j4*4];
        float2 x = *(const float2*)&S->sh1T[i][0];
        u64 p0 = pack2(x.x), p1 = pack2(x.y);
        fma2(ax[0], p0, w.x); fma2(ay[0], p0, w.y);
        fma2(ax[1], p1, w.x); fma2(ay[1], p1, w.y);
      }
      #pragma unroll
      for (int b2 = 0; b2 < 2; b2++){
        float2 l = unpack2(ax[b2]), h2 = unpack2(ay[b2]);
        *(float4*)&S->sbuf[isl][b2][j4*4] = make_float4(l.x, l.y, h2.x, h2.y);
      }
    }
    __syncthreads(); // S5
    if (g < 2){
      float s = b2[ht];
      #pragma unroll
      for (int k = 0; k < 16; k++) s += S->sbuf[k][g][ht];
      S->sct2[ht][g] = tanhf(s);
    }
    __syncthreads(); // S6

    // ---- small heads: cooperative 512-thread matvec ----
    {
      const int w16  = tid >> 5;
      const int head = w16 >> 2;
      const int c4o  = (w16 & 3) * 4;
      const float* W = (head==0)? gate_w : (head==1)? assign_w : (head==2)? cs_w : md_w;
      float4 a0 = {0,0,0,0}, a1 = {0,0,0,0};
      #pragma unroll
      for (int r = 0; r < 4; r++){
        const int i = lane*4 + r;
        float4 w4 = *(const float4*)&W[i*16 + c4o];
        float2 x2 = *(const float2*)&S->sct2[i][0];
        a0.x += x2.x*w4.x; a0.y += x2.x*w4.y; a0.z += x2.x*w4.z; a0.w += x2.x*w4.w;
        a1.x += x2.y*w4.x; a1.y += x2.y*w4.y; a1.z += x2.y*w4.z; a1.w += x2.y*w4.w;
      }
      #pragma unroll
      for (int o = 16; o; o >>= 1){
        a0.x += __shfl_xor_sync(0xffffffffu, a0.x, o);
        a0.y += __shfl_xor_sync(0xffffffffu, a0.y, o);
        a0.z += __shfl_xor_sync(0xffffffffu, a0.z, o);
        a0.w += __shfl_xor_sync(0xffffffffu, a0.w, o);
        a1.x += __shfl_xor_sync(0xffffffffu, a1.x, o);
        a1.y += __shfl_xor_sync(0xffffffffu, a1.y, o);
        a1.z += __shfl_xor_sync(0xffffffffu, a1.z, o);
        a1.w += __shfl_xor_sync(0xffffffffu, a1.w, o);
      }
      if (lane == 0){
        const float* Bp = (head==0)? gate_b : (head==1)? assign_b : (head==2)? cs_b : md_b;
        float b0 = Bp[c4o+0], b1v = Bp[c4o+1], b2v = Bp[c4o+2], b3v = Bp[c4o+3];
        S->sraw[0][head][c4o+0] = a0.x + b0;  S->sraw[0][head][c4o+1] = a0.y + b1v;
        S->sraw[0][head][c4o+2] = a0.z + b2v; S->sraw[0][head][c4o+3] = a0.w + b3v;
        S->sraw[1][head][c4o+0] = a1.x + b0;  S->sraw[1][head][c4o+1] = a1.y + b1v;
        S->sraw[1][head][c4o+2] = a1.z + b2v; S->sraw[1][head][c4o+3] = a1.w + b3v;
      }
    }
    // ---- nov/relax (4 warps) ----
    if (tid < 128){
      int w = tid >> 5; int g2 = w & 1; int rel = w >> 1;
      const float* vw = rel ? relax_w : nov_w;
      float s = 0.f;
      #pragma unroll
      for (int k = 0; k < 4; k++){ int i = lane + k*32; s += S->sct2[i][g2] * vw[i]; }
      s = rsum32(s);
      if (lane == 0){
        float r = sigm(s + (rel ? relax_b[0] : nov_b[0])) * S->sval[g2];
        if (rel) S->srl[g2] = r; else S->snv[g2] = r;
      }
    }

    // ---- cc_w [128,2048]: broadcast via shuffle (L1-free), 2-batch acc ----
    u64 A0[2] = {0,0}, A1[2] = {0,0};
    {
      float ctA[4], ctB[4];
      #pragma unroll
      for (int k = 0; k < 4; k++){
        float2 v = *(const float2*)&S->sct2[k*32 + lane][0];
        ctA[k] = v.x; ctB[k] = v.y;
      }
      const ulonglong2* W = (const ulonglong2*)cc_w;
      #pragma unroll
      for (int k = 0; k < 4; k++){
        const float ca = ctA[k], cb = ctB[k];
        const ulonglong2* Wk = W + (k*32)*512 + tid;
        #pragma unroll 8
        for (int j = 0; j < 32; j++){
          ulonglong2 wv = Wk[j*512];
          u64 p0 = pack2(__shfl_sync(0xffffffffu, ca, j));
          u64 p1 = pack2(__shfl_sync(0xffffffffu, cb, j));
          fma2(A0[0], p0, wv.x); fma2(A0[1], p0, wv.y);
          fma2(A1[0], p1, wv.x); fma2(A1[1], p1, wv.y);
        }
      }
    }

    // ---- att_w [128,128] ----
    {
      u64 ax[2] = {0,0}, ay[2] = {0,0};
      const int lo = isl * 8;
      #pragma unroll
      for (int r = 0; r < 8; r++){
        const int i = lo + r;
        ulonglong2 w = *(const ulonglong2*)&att_w[i*128 + j4*4];
        float2 x = *(const float2*)&S->sct2[i][0];
        u64 p0 = pack2(x.x), p1 = pack2(x.y);
        fma2(ax[0], p0, w.x); fma2(ay[0], p0, w.y);
        fma2(ax[1], p1, w.x); fma2(ay[1], p1, w.y);
      }
      #pragma unroll
      for (int b2 = 0; b2 < 2; b2++){
        float2 l = unpack2(ax[b2]), h2 = unpack2(ay[b2]);
        *(float4*)&S->sbuf[isl][b2][j4*4] = make_float4(l.x, l.y, h2.x, h2.y);
      }
    }
    __syncthreads(); // S7
    if (g < 2){
      float s = att_b[ht];
      #pragma unroll
      for (int k = 0; k < 16; k++) s += S->sbuf[k][g][ht];
      S->satt[g][ht] = s;
    }
    if (g == 2 && ht < 32){
      const int gb = lane >> 4;
      const int c  = lane & 15;
      float graw = S->sraw[gb][0][c];
      float araw = S->sraw[gb][1][c];
      float mx = rmax16(araw);
      float ex = expf(araw - mx);
      float sm = rsum16(ex);
      float assign = ex / sm;
      float gate = sigm(graw) * S->sval[gb];
      float ss = gate * assign;
      S->sgs[gb][c] = ss;
      float cs = splus(S->sraw[gb][2][c]) + EPSF;
      float md = tanhf(S->sraw[gb][3][c]);
      float sp = S->ssp[gb][c]; sp += ss*(cs - sp); S->ssp[gb][c] = sp;
      float m  = S->smaM[gb][c]; m += ss*md;        S->smaM[gb][c] = m;
    }
    __syncthreads(); // S8

    // ---- center update ----
    {
      const int ccC = tid >> 5, ccH = tid & 31;
      float4 bv = *(const float4*)&cc_b[ccC*128 + ccH*4];
      float4 at0 = *(const float4*)&S->satt[0][ccH*4];
      float4 at1 = *(const float4*)&S->satt[1][ccH*4];
#define CUPD(GG, AX, AT) do{ \
      float2 l  = unpack2(AX[0]); \
      float2 hh = unpack2(AX[1]); \
      float4 cand = make_float4(l.x+bv.x, l.y+bv.y, hh.x+bv.z, hh.y+bv.w); \
      float ssv = S->sgs[GG][ccC]; \
      float nv  = 0.1f * S->snv[GG]; \
      float4 v  = *(float4*)&S->sc[GG][ccC][ccH*4]; \
      v.x += ssv*(cand.x - v.x); v.x += nv*(AT.x - v.x); \
      v.y += ssv*(cand.y - v.y); v.y += nv*(AT.y - v.y); \
      v.z += ssv*(cand.z - v.z); v.z += nv*(AT.z - v.z); \
      v.w += ssv*(cand.w - v.w); v.w += nv*(AT.w - v.w); \
      *(float4*)&S->sc[GG][ccC][ccH*4] = v; }while(0)
      CUPD(0, A0, at0);
      CUPD(1, A1, at1);
#undef CUPD
    }
    __syncthreads(); // S9

    // ---- Gram: symmetric (ii<=jj), mirror write ----
    {
      const int gb = tid >> 8;
      const int p  = tid & 255;
      const int ii = p >> 4, jj = p & 15;
      if (ii <= jj){
        const float4* Aa = (const float4*)S->sc[gb][ii];
        const float4* Bv = (const float4*)S->sc[gb][jj];
        float d0=0.f, d1=0.f, d2s=0.f, d3=0.f;
        #pragma unroll 8
        for (int k = 0; k < 32; k++){
          float4 a4 = Aa[k], b4 = Bv[k];
          d0 += a4.x*b4.x; d1 += a4.y*b4.y; d2s += a4.z*b4.z; d3 += a4.w*b4.w;
        }
        float dot = (d0+d1) + (d2s+d3);
        S->smix[gb][ii][jj] = dot;
        if (ii != jj) S->smix[gb][jj][ii] = dot;
        else S->ssq[gb][ii] = dot;
      }
    }
    __syncthreads(); // S10
    {
      const int gb  = tid >> 8;
      const int row = ((tid>>5)&7)*2 + (lane >> 4);
      const int jj  = lane & 15;
      float Gij = S->smix[gb][row][jj];
      float d2v = fmaxf(S->ssq[gb][row] + S->ssq[gb][jj] - 2.f*Gij, 0.f);
      float comp = -d2v / (S->ssp[gb][row] + S->ssp[gb][jj] + EPSF) + S->smaM[gb][jj];
      float mx = rmax16(comp);
      float ex = expf(comp - mx);
      float sm = rsum16(ex);
      float mix = ex / sm;
      S->smix[gb][row][jj] = mix;
      float msp = rsum16(mix * S->ssp[gb][jj]);
      float mms = rsum16(mix * S->smaM[gb][jj]);
      if ((lane & 15) == 0){ S->sms[gb][row] = msp; S->smm[gb][row] = mms; }
    }
    __syncthreads(); // S11
    if (g < 2){
      float rl = S->srl[g];
      float cr[16];
      #pragma unroll
      for (int c = 0; c < 16; c++) cr[c] = S->sc[g][c][ht];
      #pragma unroll
      for (int i = 0; i < 16; i++){
        const float4* mr = (const float4*)S->smix[g][i];
        float4 m0 = mr[0], m1 = mr[1], m2v = mr[2], m3 = mr[3];
        float mc = m0.x*cr[0]+m0.y*cr[1]+m0.z*cr[2]+m0.w*cr[3]
                 + m1.x*cr[4]+m1.y*cr[5]+m1.z*cr[6]+m1.w*cr[7]
                 + m2v.x*cr[8]+m2v.y*cr[9]+m2v.z*cr[10]+m2v.w*cr[11]
                 + m3.x*cr[12]+m3.y*cr[13]+m3.z*cr[14]+m3.w*cr[15];
        S->sc[g][i][ht] = (1.f-rl)*cr[i] + rl*mc;
      }
    }
    if (g == 2 && ht < 32){
      const int gb = lane >> 4;
      const int c  = lane & 15;
      float rl2 = S->srl[gb];
      float sp = S->ssp[gb][c];
      float m  = S->smaM[gb][c];
      float sp2 = (1.f-rl2)*sp + rl2*S->sms[gb][c];
      float m2  = (1.f-rl2)*m  + rl2*S->smm[gb][c];
      float score = m2 + logf(1.f/(sp2+EPSF)+EPSF);
      float mx = rmax16(score);
      float ex = expf(score - mx);
      float sm = rsum16(ex);
      float ca = ex / sm;
      S->ssp[gb][c] = sp2*(1.f - 0.05f*ca*S->sval[gb]) + EPSF;
      S->smaM[gb][c] = m2;
    }
    __syncthreads(); // S12
  }

  // ---- epilogue ----
  if (g == 2 && ht < 32){
    const int gb = lane >> 4;
    const int c  = lane & 15;
    float sp = S->ssp[gb][c];
    float m  = S->smaM[gb][c];
    float score = m + logf(1.f/(sp+EPSF)+EPSF);
    float mx = rmax16(score);
    float ex = expf(score - mx);
    float sm = rsum16(ex);
    float a  = ex / sm;
    S->sal[gb][c] = a;
    float u   = rsum16(a*sp);
    float ent = rsum16(-a*logf(fmaxf(a,1e-8f)));
    float mm2 = rmax16(m);
    float en  = mm2 + logf(rsum16(expf(m - mm2)));
    float bv = a;
    int   bi = c;
    #pragma unroll
    for (int o = 8; o; o >>= 1){
      float ov = __shfl_xor_sync(0xffffffffu, bv, o);
      int   oi = __shfl_xor_sync(0xffffffffu, bi, o);
      if (ov > bv || (ov == bv && oi < bi)){ bv = ov; bi = oi; }
    }
    if (c == 0){
      S->sciT[256][gb] = u; S->sciT[258][gb] = en; S->sciT[259][gb] = ent; S->sidx[gb] = bi;
    }
  }
  __syncthreads();
  if (g < 2){
    float core = 0.f;
    #pragma unroll
    for (int c = 0; c < 16; c++) core += S->sal[g][c] * S->sc[g][c][ht];
    float dv = 0.f;
    #pragma unroll
    for (int c = 0; c < 16; c++){ float dd = S->sc[g][c][ht] - core; dv += S->sal[g][c]*dd*dd; }
    dv = rsum32(dv);
    if (lane == 0) S->sred[g][wg][2] = dv;
    float strong = S->sc[g][S->sidx[g]][ht];
    S->sciT[ht][g] = core;
    S->sciT[128+ht][g] = strong;
  }
  __syncthreads();
  if (tid < 2)
    S->sciT[257][tid] = (S->sred[tid][0][2]+S->sred[tid][1][2]+S->sred[tid][2][2]+S->sred[tid][3][2]) * (1.f/128.f);
  __syncthreads();
  {
    u64 ax[2] = {0,0}, ay[2] = {0,0};
    const int lo = isl * 16;
    #pragma unroll
    for (int r = 0; r < 16; r++){
      const int i = lo + r;
      ulonglong2 w = *(const ulonglong2*)&cw1[i*128 + j4*4];
      float2 x = *(const float2*)&S->sciT[i][0];
      u64 p0 = pack2(x.x), p1 = pack2(x.y);
      fma2(ax[0], p0, w.x); fma2(ay[0], p0, w.y);
      fma2(ax[1], p1, w.x); fma2(ay[1], p1, w.y);
    }
    if (isl < 4){
      const int i = 256 + isl;
      ulonglong2 w = *(const ulonglong2*)&cw1[i*128 + j4*4];
      float2 x = *(const float2*)&S->sciT[i][0];
      u64 p0 = pack2(x.x), p1 = pack2(x.y);
      fma2(ax[0], p0, w.x); fma2(ay[0], p0, w.y);
      fma2(ax[1], p1, w.x); fma2(ay[1], p1, w.y);
    }
    #pragma unroll
    for (int b2 = 0; b2 < 2; b2++){
      float2 l = unpack2(ax[b2]), h2 = unpack2(ay[b2]);
      *(float4*)&S->sbuf[isl][b2][j4*4] = make_float4(l.x, l.y, h2.x, h2.y);
    }
  }
  __syncthreads();
  if (g < 2){
    float s = cb1[ht];
    #pragma unroll
    for (int k = 0; k < 16; k++) s += S->sbuf[k][g][ht];
    S->sh1T[ht][g] = 0.5f * s * (1.f + erff(s * 0.70710678118654752440f));
  }
  __syncthreads();
  if (g < 2 && ht < 8){
    float s = cb2[ht];
    #pragma unroll 4
    for (int i = 0; i < 128; i++) s += S->sh1T[i][g] * cw2[i*8 + ht];
    out[b*8 + ht] = s;
  }
}

extern "C" void kernel_launch(void* const* d_in, const int* in_sizes, int n_in,
                              void* d_out, int out_size){
  (void)in_sizes; (void)n_in; (void)out_size;
  cudaFuncSetAttribute(cfrm_kernel, cudaFuncAttributeMaxDynamicSharedMemorySize, (int)sizeof(Smem));
  cfrm_kernel<<<64, 512, sizeof(Smem)>>>(
    (const int*)  d_in[0],  (const float*)d_in[1],  (const float*)d_in[2],  (const float*)d_in[3],
    (const float*)d_in[4],  (const float*)d_in[5],  (const float*)d_in[6],  (const float*)d_in[7],
    (const float*)d_in[8],  (const float*)d_in[9],  (const float*)d_in[10], (const float*)d_in[11],
    (const float*)d_in[12], (const float*)d_in[13], (const float*)d_in[14], (const float*)d_in[15],
    (const float*)d_in[16], (const float*)d_in[17], (const float*)d_in[18], (const float*)d_in[19],
    (const float*)d_in[20], (const float*)d_in[21], (const float*)d_in[22], (const float*)d_in[23],
    (const float*)d_in[24], (const float*)d_in[25], (const float*)d_in[26], (const float*)d_in[27],
    (float*)d_out);
}

// round 16
// speedup vs baseline: 1.3043x; 1.3043x over previous
#include <cuda_runtime.h>
#include <math.h>

#define EPSF 1e-4f
typedef unsigned long long u64;

__device__ __forceinline__ u64 pack2(float x){
  u64 r; unsigned xi = __float_as_uint(x);
  asm("mov.b64 %0, {%1, %1};" : "=l"(r) : "r"(xi));
  return r;
}
__device__ __forceinline__ void fma2(u64 &acc, u64 a, u64 b){
  asm("fma.rn.f32x2 %0, %1, %2, %0;" : "+l"(acc) : "l"(a), "l"(b));
}
__device__ __forceinline__ float2 unpack2(u64 v){
  unsigned lo, hi;
  asm("mov.b64 {%0, %1}, %2;" : "=r"(lo), "=r"(hi) : "l"(v));
  return make_float2(__uint_as_float(lo), __uint_as_float(hi));
}
__device__ __forceinline__ float rsum32(float v){
  #pragma unroll
  for (int o=16;o;o>>=1) v += __shfl_xor_sync(0xffffffffu, v, o);
  return v;
}
__device__ __forceinline__ float rsum16(float v){
  #pragma unroll
  for (int o=8;o;o>>=1) v += __shfl_xor_sync(0xffffffffu, v, o);
  return v;
}
__device__ __forceinline__ float rmax16(float v){
  #pragma unroll
  for (int o=8;o;o>>=1) v = fmaxf(v, __shfl_xor_sync(0xffffffffu, v, o));
  return v;
}
__device__ __forceinline__ float sigm(float x){ return 1.f/(1.f+expf(-x)); }
__device__ __forceinline__ float splus(float x){ return fmaxf(x,0.f)+log1pf(expf(-fabsf(x))); }

struct Smem {
  float sci[260];
  float sh1[128];
  float sct[128];
  float sc[16][132];
  float smix[16][16];
  float satt[128];
  float sbuf[16][128];
  float ssp[16], smaM[16], sal[16], sgs[16];
  float ssq[16], sms[16], smm[16];
  float sraw[4][16];
  float sred[4][3];
  float snv, srl, sval;
  int   sidx;
};

__global__ void __launch_bounds__(512,1) cfrm_kernel(
   const int* __restrict__ tokens, const float* __restrict__ emb,
   const float* __restrict__ ln_g, const float* __restrict__ ln_b,
   const float* __restrict__ w1, const float* __restrict__ b1,
   const float* __restrict__ w2, const float* __restrict__ b2,
   const float* __restrict__ gate_w, const float* __restrict__ gate_b,
   const float* __restrict__ assign_w, const float* __restrict__ assign_b,
   const float* __restrict__ nov_w, const float* __restrict__ nov_b,
   const float* __restrict__ relax_w, const float* __restrict__ relax_b,
   const float* __restrict__ cc_w, const float* __restrict__ cc_b,
   const float* __restrict__ cs_w, const float* __restrict__ cs_b,
   const float* __restrict__ md_w, const float* __restrict__ md_b,
   const float* __restrict__ att_w, const float* __restrict__ att_b,
   const float* __restrict__ cw1, const float* __restrict__ cb1,
   const float* __restrict__ cw2, const float* __restrict__ cb2,
   float* __restrict__ out)
{
  extern __shared__ __align__(128) char smem_raw[];
  Smem* S = (Smem*)smem_raw;

  const int tid  = threadIdx.x;
  const int ht   = tid & 127;
  const int lane = tid & 31;
  const int wid  = tid >> 5;
  const int b    = blockIdx.x;

  const int j4  = tid & 31;
  const int isl = tid >> 5;

  for (int i = tid; i < 16*132; i += 512) ((float*)S->sc)[i] = 0.f;
  if (tid < 16){ S->ssp[tid] = 1.f; S->smaM[tid] = 0.f; }
  __syncthreads();

  for (int t = 0; t < 512; t++){
    if (tid < 128){
      const int tok = tokens[b*512 + t];
      if (tid == 0) S->sval = (tok != 0) ? 1.f : 0.f;
      const float e = emb[tok*128 + tid];
      float ps = rsum32(e);
      float pq = rsum32(e*e);
      if (lane == 0){ S->sred[wid][0] = ps; S->sred[wid][1] = pq; }
      S->sci[tid] = e;
    }
    if (wid == 8){  // full warp; both 16-lane halves duplicate
      const int c = lane & 15;
      float sp = S->ssp[c];
      float m  = S->smaM[c];
      float score = m + logf(1.f/(sp+EPSF)+EPSF);
      float mx = rmax16(score);
      float ex = expf(score - mx);
      float sm = rsum16(ex);
      float a  = ex / sm;
      S->sal[c] = a;
      float u   = rsum16(a*sp);
      float ent = rsum16(-a*logf(fmaxf(a,1e-8f)));
      float mm2 = rmax16(m);
      float en  = mm2 + logf(rsum16(expf(m - mm2)));
      if (lane == 0){ S->sci[256] = u; S->sci[258] = en; S->sci[259] = ent; }
    }
    __syncthreads(); // S1
    if (tid < 128){
      const float e = S->sci[tid];
      float mu = (S->sred[0][0]+S->sred[1][0]+S->sred[2][0]+S->sred[3][0]) * (1.f/128.f);
      float mq = (S->sred[0][1]+S->sred[1][1]+S->sred[2][1]+S->sred[3][1]) * (1.f/128.f);
      float var = mq - mu*mu;
      float te = (e - mu) * rsqrtf(var + 1e-5f) * ln_g[tid] + ln_b[tid];
      S->sci[tid] = te;
      float core = 0.f;
      #pragma unroll
      for (int c = 0; c < 16; c++) core += S->sal[c] * S->sc[c][tid];
      S->sci[128+tid] = core;
      float dv = 0.f;
      #pragma unroll
      for (int c = 0; c < 16; c++){ float dd = S->sc[c][tid] - core; dv += S->sal[c]*dd*dd; }
      dv = rsum32(dv);
      if (lane == 0) S->sred[wid][2] = dv;
    }
    __syncthreads(); // S2a
    if (tid == 0)
      S->sci[257] = (S->sred[0][2]+S->sred[1][2]+S->sred[2][2]+S->sred[3][2]) * (1.f/128.f);
    __syncthreads(); // S2b

    // ---- w1 [260,128] ----
    {
      u64 ax = 0, ay = 0;
      const int lo = isl * 16;
      #pragma unroll
      for (int r = 0; r < 16; r++){
        const int i = lo + r;
        ulonglong2 w = *(const ulonglong2*)&w1[i*128 + j4*4];
        u64 p0 = pack2(S->sci[i]);
        fma2(ax, p0, w.x); fma2(ay, p0, w.y);
      }
      if (isl < 4){
        const int i = 256 + isl;
        ulonglong2 w = *(const ulonglong2*)&w1[i*128 + j4*4];
        u64 p0 = pack2(S->sci[i]);
        fma2(ax, p0, w.x); fma2(ay, p0, w.y);
      }
      float2 l = unpack2(ax), h2 = unpack2(ay);
      *(float4*)&S->sbuf[isl][j4*4] = make_float4(l.x, l.y, h2.x, h2.y);
    }
    __syncthreads(); // S3
    if (tid < 128){
      float s = b1[tid];
      #pragma unroll
      for (int k = 0; k < 16; k++) s += S->sbuf[k][tid];
      S->sh1[tid] = tanhf(s);
    }
    __syncthreads(); // S4

    // ---- w2 [128,128] ----
    {
      u64 ax = 0, ay = 0;
      const int lo = isl * 8;
      #pragma unroll
      for (int r = 0; r < 8; r++){
        const int i = lo + r;
        ulonglong2 w = *(const ulonglong2*)&w2[i*128 + j4*4];
        u64 p0 = pack2(S->sh1[i]);
        fma2(ax, p0, w.x); fma2(ay, p0, w.y);
      }
      float2 l = unpack2(ax), h2 = unpack2(ay);
      *(float4*)&S->sbuf[isl][j4*4] = make_float4(l.x, l.y, h2.x, h2.y);
    }
    __syncthreads(); // S5
    if (tid < 128){
      float s = b2[tid];
      #pragma unroll
      for (int k = 0; k < 16; k++) s += S->sbuf[k][tid];
      S->sct[tid] = tanhf(s);
    }
    __syncthreads(); // S6

    // ---- small heads: cooperative 512-thread matvec ----
    {
      const int head = wid >> 2;
      const int c4o  = (wid & 3) * 4;
      const float* W = (head==0)? gate_w : (head==1)? assign_w : (head==2)? cs_w : md_w;
      float4 a0 = {0,0,0,0};
      #pragma unroll
      for (int r = 0; r < 4; r++){
        const int i = lane*4 + r;
        float4 w4 = *(const float4*)&W[i*16 + c4o];
        float xv = S->sct[i];
        a0.x += xv*w4.x; a0.y += xv*w4.y; a0.z += xv*w4.z; a0.w += xv*w4.w;
      }
      #pragma unroll
      for (int o = 16; o; o >>= 1){
        a0.x += __shfl_xor_sync(0xffffffffu, a0.x, o);
        a0.y += __shfl_xor_sync(0xffffffffu, a0.y, o);
        a0.z += __shfl_xor_sync(0xffffffffu, a0.z, o);
        a0.w += __shfl_xor_sync(0xffffffffu, a0.w, o);
      }
      if (lane == 0){
        const float* Bp = (head==0)? gate_b : (head==1)? assign_b : (head==2)? cs_b : md_b;
        S->sraw[head][c4o+0] = a0.x + Bp[c4o+0];
        S->sraw[head][c4o+1] = a0.y + Bp[c4o+1];
        S->sraw[head][c4o+2] = a0.z + Bp[c4o+2];
        S->sraw[head][c4o+3] = a0.w + Bp[c4o+3];
      }
    }
    // ---- nov/relax (2 warps, full warps) ----
    if (tid < 64){
      int rel = wid;
      const float* vw = rel ? relax_w : nov_w;
      float s = 0.f;
      #pragma unroll
      for (int k = 0; k < 4; k++){ int i = lane + k*32; s += S->sct[i] * vw[i]; }
      s = rsum32(s);
      if (lane == 0){
        float r = sigm(s + (rel ? relax_b[0] : nov_b[0])) * S->sval;
        if (rel) S->srl = r; else S->snv = r;
      }
    }

    // ---- cc_w [128,2048]: unroll 16 ----
    u64 A0[2] = {0,0};
    {
      const ulonglong2* W = (const ulonglong2*)cc_w;
      #pragma unroll 16
      for (int i = 0; i < 128; i++){
        ulonglong2 wv = W[i*512 + tid];
        u64 p0 = pack2(S->sct[i]);
        fma2(A0[0], p0, wv.x); fma2(A0[1], p0, wv.y);
      }
    }

    // ---- att_w [128,128] ----
    {
      u64 ax = 0, ay = 0;
      const int lo = isl * 8;
      #pragma unroll
      for (int r = 0; r < 8; r++){
        const int i = lo + r;
        ulonglong2 w = *(const ulonglong2*)&att_w[i*128 + j4*4];
        u64 p0 = pack2(S->sct[i]);
        fma2(ax, p0, w.x); fma2(ay, p0, w.y);
      }
      float2 l = unpack2(ax), h2 = unpack2(ay);
      *(float4*)&S->sbuf[isl][j4*4] = make_float4(l.x, l.y, h2.x, h2.y);
    }
    __syncthreads(); // S7
    if (tid < 128){
      float s = att_b[tid];
      #pragma unroll
      for (int k = 0; k < 16; k++) s += S->sbuf[k][tid];
      S->satt[tid] = s;
    }
    if (wid == 8){  // full warp
      const int c = lane & 15;
      float graw = S->sraw[0][c];
      float araw = S->sraw[1][c];
      float mx = rmax16(araw);
      float ex = expf(araw - mx);
      float sm = rsum16(ex);
      float assign = ex / sm;
      float gate = sigm(graw) * S->sval;
      float ss = gate * assign;
      S->sgs[c] = ss;
      float cs = splus(S->sraw[2][c]) + EPSF;
      float md = tanhf(S->sraw[3][c]);
      float sp = S->ssp[c]; sp += ss*(cs - sp); S->ssp[c] = sp;
      float m  = S->smaM[c]; m += ss*md;        S->smaM[c] = m;
    }
    __syncthreads(); // S8

    // ---- center update ----
    {
      const int ccC = tid >> 5, ccH = tid & 31;
      float4 bv = *(const float4*)&cc_b[ccC*128 + ccH*4];
      float4 at = *(const float4*)&S->satt[ccH*4];
      float2 l  = unpack2(A0[0]);
      float2 hh = unpack2(A0[1]);
      float4 cand = make_float4(l.x+bv.x, l.y+bv.y, hh.x+bv.z, hh.y+bv.w);
      float ssv = S->sgs[ccC];
      float nv  = 0.1f * S->snv;
      float4 v  = *(float4*)&S->sc[ccC][ccH*4];
      v.x += ssv*(cand.x - v.x); v.x += nv*(at.x - v.x);
      v.y += ssv*(cand.y - v.y); v.y += nv*(at.y - v.y);
      v.z += ssv*(cand.z - v.z); v.z += nv*(at.z - v.z);
      v.w += ssv*(cand.w - v.w); v.w += nv*(at.w - v.w);
      *(float4*)&S->sc[ccC][ccH*4] = v;
    }
    __syncthreads(); // S9

    // ---- Gram: tid<256 (full warps 0-7) ----
    if (tid < 256){
      const int ii = tid >> 4, jj = tid & 15;
      const float4* Aa = (const float4*)S->sc[ii];
      const float4* Bv = (const float4*)S->sc[jj];
      float d0=0.f, d1=0.f, d2s=0.f, d3=0.f;
      #pragma unroll 8
      for (int k = 0; k < 32; k++){
        float4 a4 = Aa[k], b4 = Bv[k];
        d0 += a4.x*b4.x; d1 += a4.y*b4.y; d2s += a4.z*b4.z; d3 += a4.w*b4.w;
      }
      float dot = (d0+d1) + (d2s+d3);
      S->smix[ii][jj] = dot;
      if (ii == jj) S->ssq[ii] = dot;
    }
    __syncthreads(); // S10
    if (tid < 256){
      const int row = (tid>>5)*2 + (lane >> 4);
      const int jj  = lane & 15;
      float Gij = S->smix[row][jj];
      float d2v = fmaxf(S->ssq[row] + S->ssq[jj] - 2.f*Gij, 0.f);
      float comp = -d2v / (S->ssp[row] + S->ssp[jj] + EPSF) + S->smaM[jj];
      float mx = rmax16(comp);
      float ex = expf(comp - mx);
      float sm = rsum16(ex);
      float mix = ex / sm;
      S->smix[row][jj] = mix;
      float msp = rsum16(mix * S->ssp[jj]);
      float mms = rsum16(mix * S->smaM[jj]);
      if ((lane & 15) == 0){ S->sms[row] = msp; S->smm[row] = mms; }
    }
    __syncthreads(); // S11
    {
      const int igrp = tid >> 7;
      float cr[16];
      #pragma unroll
      for (int c = 0; c < 16; c++) cr[c] = S->sc[c][ht];
      float rl = S->srl;
      float res[4];
      #pragma unroll
      for (int q = 0; q < 4; q++){
        const int i = igrp*4 + q;
        const float4* mr = (const float4*)S->smix[i];
        float4 m0 = mr[0], m1 = mr[1], m2v = mr[2], m3 = mr[3];
        float mc = m0.x*cr[0]+m0.y*cr[1]+m0.z*cr[2]+m0.w*cr[3]
                 + m1.x*cr[4]+m1.y*cr[5]+m1.z*cr[6]+m1.w*cr[7]
                 + m2v.x*cr[8]+m2v.y*cr[9]+m2v.z*cr[10]+m2v.w*cr[11]
                 + m3.x*cr[12]+m3.y*cr[13]+m3.z*cr[14]+m3.w*cr[15];
        res[q] = (1.f-rl)*cr[i] + rl*mc;
      }
      __syncthreads(); // S11b
      #pragma unroll
      for (int q = 0; q < 4; q++) S->sc[igrp*4 + q][ht] = res[q];
    }
    if (wid == 8){  // full warp
      const int c = lane & 15;
      float rl2 = S->srl;
      float sp = S->ssp[c];
      float m  = S->smaM[c];
      float sp2 = (1.f-rl2)*sp + rl2*S->sms[c];
      float m2  = (1.f-rl2)*m  + rl2*S->smm[c];
      float score = m2 + logf(1.f/(sp2+EPSF)+EPSF);
      float mx = rmax16(score);
      float ex = expf(score - mx);
      float sm = rsum16(ex);
      float ca = ex / sm;
      S->ssp[c] = sp2*(1.f - 0.05f*ca*S->sval) + EPSF;
      S->smaM[c] = m2;
    }
    __syncthreads(); // S12
  }

  // ---- epilogue ----
  if (wid == 8){  // full warp
    const int c = lane & 15;
    float sp = S->ssp[c];
    float m  = S->smaM[c];
    float score = m + logf(1.f/(sp+EPSF)+EPSF);
    float mx = rmax16(score);
    float ex = expf(score - mx);
    float sm = rsum16(ex);
    float a  = ex / sm;
    S->sal[c] = a;
    float u   = rsum16(a*sp);
    float ent = rsum16(-a*logf(fmaxf(a,1e-8f)));
    float mm2 = rmax16(m);
    float en  = mm2 + logf(rsum16(expf(m - mm2)));
    float bv = a;
    int   bi = c;
    #pragma unroll
    for (int o = 8; o; o >>= 1){
      float ov = __shfl_xor_sync(0xffffffffu, bv, o);
      int   oi = __shfl_xor_sync(0xffffffffu, bi, o);
      if (ov > bv || (ov == bv && oi < bi)){ bv = ov; bi = oi; }
    }
    if (lane == 0){
      S->sci[256] = u; S->sci[258] = en; S->sci[259] = ent; S->sidx = bi;
    }
  }
  __syncthreads();
  if (tid < 128){
    float core = 0.f;
    #pragma unroll
    for (int c = 0; c < 16; c++) core += S->sal[c] * S->sc[c][tid];
    float dv = 0.f;
    #pragma unroll
    for (int c = 0; c < 16; c++){ float dd = S->sc[c][tid] - core; dv += S->sal[c]*dd*dd; }
    dv = rsum32(dv);
    if (lane == 0) S->sred[wid][2] = dv;
    float strong = S->sc[S->sidx][tid];
    S->sci[tid] = core;
    S->sci[128+tid] = strong;
  }
  __syncthreads();
  if (tid == 0)
    S->sci[257] = (S->sred[0][2]+S->sred[1][2]+S->sred[2][2]+S->sred[3][2]) * (1.f/128.f);
  __syncthreads();
  {
    u64 ax = 0, ay = 0;
    const int lo = isl * 16;
    #pragma unroll
    for (int r = 0; r < 16; r++){
      const int i = lo + r;
      ulonglong2 w = *(const ulonglong2*)&cw1[i*128 + j4*4];
      u64 p0 = pack2(S->sci[i]);
      fma2(ax, p0, w.x); fma2(ay, p0, w.y);
    }
    if (isl < 4){
      const int i = 256 + isl;
      ulonglong2 w = *(const ulonglong2*)&cw1[i*128 + j4*4];
      u64 p0 = pack2(S->sci[i]);
      fma2(ax, p0, w.x); fma2(ay, p0, w.y);
    }
    float2 l = unpack2(ax), h2 = unpack2(ay);
    *(float4*)&S->sbuf[isl][j4*4] = make_float4(l.x, l.y, h2.x, h2.y);
  }
  __syncthreads();
  if (tid < 128){
    float s = cb1[tid];
    #pragma unroll
    for (int k = 0; k < 16; k++) s += S->sbuf[k][tid];
    S->sh1[tid] = 0.5f * s * (1.f + erff(s * 0.70710678118654752440f));
  }
  __syncthreads();
  if (tid < 8){
    float s = cb2[tid];
    #pragma unroll 4
    for (int i = 0; i < 128; i++) s += S->sh1[i] * cw2[i*8 + tid];
    out[b*8 + tid] = s;
  }
}

extern "C" void kernel_launch(void* const* d_in, const int* in_sizes, int n_in,
                              void* d_out, int out_size){
  (void)in_sizes; (void)n_in; (void)out_size;
  cudaFuncSetAttribute(cfrm_kernel, cudaFuncAttributeMaxDynamicSharedMemorySize, (int)sizeof(Smem));
  cfrm_kernel<<<128, 512, sizeof(Smem)>>>(
    (const int*)  d_in[0],  (const float*)d_in[1],  (const float*)d_in[2],  (const float*)d_in[3],
    (const float*)d_in[4],  (const float*)d_in[5],  (const float*)d_in[6],  (const float*)d_in[7],
    (const float*)d_in[8],  (const float*)d_in[9],  (const float*)d_in[10], (const float*)d_in[11],
    (const float*)d_in[12], (const float*)d_in[13], (const float*)d_in[14], (const float*)d_in[15],
    (const float*)d_in[16], (const float*)d_in[17], (const float*)d_in[18], (const float*)d_in[19],
    (const float*)d_in[20], (const float*)d_in[21], (const float*)d_in[22], (const float*)d_in[23],
    (const float*)d_in[24], (const float*)d_in[25], (const float*)d_in[26], (const float*)d_in[27],
    (float*)d_out);
}